// round 7
// baseline (speedup 1.0000x reference)
#include <cuda_runtime.h>
#include <cuda_fp16.h>
#include <cstdint>

// out[b,o] = sum_i tanh(x[b,i]*t) * W[o,i],  W = sum_p coef[o,i,p]
// B=131072, I=O=128. fp32 in/out.
//
// mma.sync.m16n8k16 fp16 (fp32 accum), fp16 W (rel_err ~2.7e-4).
// R5 base + smem-restaged coalesced epilogue (FIXED: STG at logical offset,
// LDS at swizzled offset) + uint4 B loads + paired-RCP tanh.

static constexpr int IDIM = 128;
static constexpr int ODIM = 128;
static constexpr int TILE_M = 64;

// B fragments, paired layout: block (kt, nt2) of 32 lanes x uint4 =
// [ntg=2*nt2 reg0, reg1, ntg=2*nt2+1 reg0, reg1]. 32KB, L1/L2-hot.
__device__ uint32_t g_BF[8 * 8 * 32 * 4];

// ---------------------------------------------------------------------------
__global__ void prep_w_kernel(const float* __restrict__ coef) {
    int idx = blockIdx.x * blockDim.x + threadIdx.x;   // 0..8191
    int nt = idx >> 9;
    int kt = (idx >> 6) & 7;
    int lane = (idx >> 1) & 31;
    int reg = idx & 1;
    int n = nt * 8 + (lane >> 2);
    int k = kt * 16 + (lane & 3) * 2 + reg * 8;

    const float4* c0 = reinterpret_cast<const float4*>(coef + ((size_t)n * 128 + k) * 16);
    const float4* c1 = reinterpret_cast<const float4*>(coef + ((size_t)n * 128 + k + 1) * 16);
    float4 v[8];
#pragma unroll
    for (int j = 0; j < 4; j++) v[j] = c0[j];
#pragma unroll
    for (int j = 0; j < 4; j++) v[4 + j] = c1[j];
    float s0 = 0.f, s1 = 0.f;
#pragma unroll
    for (int j = 0; j < 4; j++) s0 += (v[j].x + v[j].y) + (v[j].z + v[j].w);
#pragma unroll
    for (int j = 0; j < 4; j++) s1 += (v[4 + j].x + v[4 + j].y) + (v[4 + j].z + v[4 + j].w);
    __half2 hh = __floats2half2_rn(s0, s1);
    int pos = ((kt * 8 + (nt >> 1)) * 32 + lane) * 4 + (nt & 1) * 2 + reg;
    g_BF[pos] = *reinterpret_cast<uint32_t*>(&hh);
}

// ---------------------------------------------------------------------------
// paired tanh: 2 EX2 + 1 RCP for two elements (exact algebra).
// ---------------------------------------------------------------------------
__device__ __forceinline__ void tanh2(float v0, float v1, float t,
                                      float& r0, float& r1) {
    v0 = fminf(fmaxf(v0 * t, -9.f), 9.f);
    v1 = fminf(fmaxf(v1 * t, -9.f), 9.f);
    float e0, e1;
    asm("ex2.approx.f32 %0, %1;" : "=f"(e0) : "f"(v0 * 2.88539008f));  // e^{2v}
    asm("ex2.approx.f32 %0, %1;" : "=f"(e1) : "f"(v1 * 2.88539008f));
    float p0 = e0 + 1.f, p1 = e1 + 1.f;
    float r;
    asm("rcp.approx.f32 %0, %1;" : "=f"(r) : "f"(p0 * p1));
    r0 = (e0 - 1.f) * p1 * r;
    r1 = (e1 - 1.f) * p0 * r;
}

__device__ __forceinline__ uint32_t pack_h2(float a, float b) {
    __half2 h = __floats2half2_rn(a, b);
    return *reinterpret_cast<uint32_t*>(&h);
}

#define MMA16816(d0, d1, d2, d3, a0, a1, a2, a3, b0, b1)                      \
    asm volatile(                                                             \
        "mma.sync.aligned.m16n8k16.row.col.f32.f16.f16.f32 "                  \
        "{%0,%1,%2,%3}, {%4,%5,%6,%7}, {%8,%9}, {%0,%1,%2,%3};"               \
        : "+f"(d0), "+f"(d1), "+f"(d2), "+f"(d3)                              \
        : "r"(a0), "r"(a1), "r"(a2), "r"(a3), "r"(b0), "r"(b1))

#define LDMATRIX_X4(a0, a1, a2, a3, addr)                                     \
    asm volatile(                                                             \
        "ldmatrix.sync.aligned.m8n8.x4.shared.b16 {%0,%1,%2,%3}, [%4];"       \
        : "=r"(a0), "=r"(a1), "=r"(a2), "=r"(a3) : "r"(addr))

// SMEM: 16KB. Phase 1: A tile 64 rows x 256B (XOR-16B swizzle).
// Epilogue: reused as 32 rows x 512B fp32 staging (XOR-32B swizzle).
static constexpr int SMEM_TOTAL = 16384;

// ---------------------------------------------------------------------------
__global__ __launch_bounds__(256, 4) void fused_tanh_gemm_kernel(
    const float* __restrict__ x, const float* __restrict__ tanh_range,
    float* __restrict__ out)
{
    extern __shared__ __align__(16) char smem[];
    uint32_t sbase;
    asm("{ .reg .u64 t; cvta.to.shared.u64 t, %1; cvt.u32.u64 %0, t; }"
        : "=r"(sbase) : "l"(smem));

    const int tid = threadIdx.x;
    const int lane = tid & 31;
    const int wid = tid >> 5;
    const int mgroup = wid >> 2;
    const int ngroup = wid & 3;
    const size_t rowBase = (size_t)blockIdx.x * TILE_M;

    // ---- stage 1: coalesced load + tanh + swizzled STS.64 ----
    {
        const float t = __ldg(tanh_range);
        const float4* x4 = reinterpret_cast<const float4*>(x + rowBase * IDIM);
#pragma unroll
        for (int p = 0; p < 8; p++) {
            int row = wid * 8 + p;
            float4 v = __ldcs(&x4[row * 32 + lane]);
            float t0, t1, t2, t3;
            tanh2(v.x, v.y, t, t0, t1);
            tanh2(v.z, v.w, t, t2, t3);
            uint2 hp;
            hp.x = pack_h2(t0, t1);
            hp.y = pack_h2(t2, t3);
            uint32_t byte = (uint32_t)row * 256 + ((lane * 8) ^ ((row & 7) << 4));
            *reinterpret_cast<uint2*>(smem + byte) = hp;
        }
    }
    __syncthreads();

    // ---- stage 2: MMA ----
    float acc[2][4][4];
#pragma unroll
    for (int a = 0; a < 2; a++)
#pragma unroll
        for (int b = 0; b < 4; b++)
#pragma unroll
            for (int cc = 0; cc < 4; cc++) acc[a][b][cc] = 0.f;

    const int lrow = ((lane >> 3) & 1) * 8 + (lane & 7);
    const uint32_t chi = (uint32_t)((lane >> 4) << 4);
    const uint32_t sw = (uint32_t)((lane & 7) << 4);
    const uint4* gb = reinterpret_cast<const uint4*>(g_BF);

#pragma unroll
    for (int kt = 0; kt < 8; kt++) {
        uint32_t a0[2], a1[2], a2[2], a3[2];
#pragma unroll
        for (int mt = 0; mt < 2; mt++) {
            int mtg = mgroup * 2 + mt;
            int r = mtg * 16 + lrow;
            uint32_t addr = sbase + (uint32_t)r * 256 + (((uint32_t)kt * 32 + chi) ^ sw);
            LDMATRIX_X4(a0[mt], a1[mt], a2[mt], a3[mt], addr);
        }
#pragma unroll
        for (int j = 0; j < 2; j++) {               // nt pair j -> nt = 2j, 2j+1
            uint4 q = __ldg(&gb[(size_t)((kt * 8 + ngroup * 2 + j) * 32 + lane)]);
#pragma unroll
            for (int mt = 0; mt < 2; mt++) {
                MMA16816(acc[mt][2 * j][0], acc[mt][2 * j][1],
                         acc[mt][2 * j][2], acc[mt][2 * j][3],
                         a0[mt], a1[mt], a2[mt], a3[mt], q.x, q.y);
                MMA16816(acc[mt][2 * j + 1][0], acc[mt][2 * j + 1][1],
                         acc[mt][2 * j + 1][2], acc[mt][2 * j + 1][3],
                         a0[mt], a1[mt], a2[mt], a3[mt], q.z, q.w);
            }
        }
    }

    // ---- epilogue: restage via SMEM (two 32-row halves), coalesced STG ----
#pragma unroll
    for (int h = 0; h < 2; h++) {
        __syncthreads();   // A-tile / previous-half reads complete
        if (mgroup == h) {
#pragma unroll
            for (int mt = 0; mt < 2; mt++) {
                int lr = mt * 16 + (lane >> 2);      // 0..15 within half
                int lr2 = lr + 8;
#pragma unroll
                for (int nt = 0; nt < 4; nt++) {
                    uint32_t cbyte = (uint32_t)(ngroup * 32 + nt * 8 + ((lane & 3) << 1)) * 4;
                    *reinterpret_cast<float2*>(
                        smem + lr * 512 + (cbyte ^ ((uint32_t)(lr & 7) << 5)))
                        = make_float2(acc[mt][nt][0], acc[mt][nt][1]);
                    *reinterpret_cast<float2*>(
                        smem + lr2 * 512 + (cbyte ^ ((uint32_t)(lr2 & 7) << 5)))
                        = make_float2(acc[mt][nt][2], acc[mt][nt][3]);
                }
            }
        }
        __syncthreads();
        float* obase = out + (rowBase + (size_t)h * 32) * ODIM;
#pragma unroll
        for (int it = 0; it < 4; it++) {
            int idx = tid + it * 256;
            int row = idx >> 5;
            int u = idx & 31;
            uint32_t logical = (uint32_t)u * 16;                       // gmem offset
            uint32_t swz = logical ^ ((uint32_t)(row & 7) << 5);       // smem offset
            uint4 val = *reinterpret_cast<const uint4*>(smem + row * 512 + swz);
            __stcs(reinterpret_cast<uint4*>(
                       reinterpret_cast<char*>(obase + (size_t)row * ODIM) + logical),
                   val);
        }
    }
}

// ---------------------------------------------------------------------------
extern "C" void kernel_launch(void* const* d_in, const int* in_sizes, int n_in,
                              void* d_out, int out_size) {
    const float* x = (const float*)d_in[0];
    const float* coef = (const float*)d_in[1];
    const float* tr = (const float*)d_in[2];
    float* out = (float*)d_out;

    cudaFuncSetAttribute(fused_tanh_gemm_kernel,
                         cudaFuncAttributeMaxDynamicSharedMemorySize, SMEM_TOTAL);

    prep_w_kernel<<<32, 256>>>(coef);

    int rows = in_sizes[0] / IDIM;     // 131072
    int grid = rows / TILE_M;          // 2048
    fused_tanh_gemm_kernel<<<grid, 256, SMEM_TOTAL>>>(x, tr, out);
}

// round 8
// speedup vs baseline: 1.0615x; 1.0615x over previous
#include <cuda_runtime.h>
#include <cuda_fp16.h>
#include <cstdint>

// out[b,o] = sum_i tanh(x[b,i]*t) * W[o,i],  W = sum_p coef[o,i,p]
// B=131072, I=O=128. fp32 in/out.
//
// mma.sync.m16n8k16 fp16 (fp32 accum), fp16 W (rel_err ~2.7e-4).
// R7 base + PDL overlap of prep_w with GEMM prologue + single-restage epilogue.

static constexpr int IDIM = 128;
static constexpr int ODIM = 128;
static constexpr int TILE_M = 64;

// B fragments, paired layout: block (kt, nt2) of 32 lanes x uint4 =
// [ntg=2*nt2 reg0, reg1, ntg=2*nt2+1 reg0, reg1]. 32KB, L1/L2-hot.
__device__ uint32_t g_BF[8 * 8 * 32 * 4];

// ---------------------------------------------------------------------------
__global__ void prep_w_kernel(const float* __restrict__ coef) {
    int idx = blockIdx.x * blockDim.x + threadIdx.x;   // 0..8191
    int nt = idx >> 9;
    int kt = (idx >> 6) & 7;
    int lane = (idx >> 1) & 31;
    int reg = idx & 1;
    int n = nt * 8 + (lane >> 2);
    int k = kt * 16 + (lane & 3) * 2 + reg * 8;

    const float4* c0 = reinterpret_cast<const float4*>(coef + ((size_t)n * 128 + k) * 16);
    const float4* c1 = reinterpret_cast<const float4*>(coef + ((size_t)n * 128 + k + 1) * 16);
    float4 v[8];
#pragma unroll
    for (int j = 0; j < 4; j++) v[j] = c0[j];
#pragma unroll
    for (int j = 0; j < 4; j++) v[4 + j] = c1[j];
    float s0 = 0.f, s1 = 0.f;
#pragma unroll
    for (int j = 0; j < 4; j++) s0 += (v[j].x + v[j].y) + (v[j].z + v[j].w);
#pragma unroll
    for (int j = 0; j < 4; j++) s1 += (v[4 + j].x + v[4 + j].y) + (v[4 + j].z + v[4 + j].w);
    __half2 hh = __floats2half2_rn(s0, s1);
    int pos = ((kt * 8 + (nt >> 1)) * 32 + lane) * 4 + (nt & 1) * 2 + reg;
    g_BF[pos] = *reinterpret_cast<uint32_t*>(&hh);
}

// ---------------------------------------------------------------------------
// paired tanh: 2 EX2 + 1 RCP for two elements (exact algebra).
// ---------------------------------------------------------------------------
__device__ __forceinline__ void tanh2(float v0, float v1, float t,
                                      float& r0, float& r1) {
    v0 = fminf(fmaxf(v0 * t, -9.f), 9.f);
    v1 = fminf(fmaxf(v1 * t, -9.f), 9.f);
    float e0, e1;
    asm("ex2.approx.f32 %0, %1;" : "=f"(e0) : "f"(v0 * 2.88539008f));  // e^{2v}
    asm("ex2.approx.f32 %0, %1;" : "=f"(e1) : "f"(v1 * 2.88539008f));
    float p0 = e0 + 1.f, p1 = e1 + 1.f;
    float r;
    asm("rcp.approx.f32 %0, %1;" : "=f"(r) : "f"(p0 * p1));
    r0 = (e0 - 1.f) * p1 * r;
    r1 = (e1 - 1.f) * p0 * r;
}

__device__ __forceinline__ uint32_t pack_h2(float a, float b) {
    __half2 h = __floats2half2_rn(a, b);
    return *reinterpret_cast<uint32_t*>(&h);
}

#define MMA16816(d0, d1, d2, d3, a0, a1, a2, a3, b0, b1)                      \
    asm volatile(                                                             \
        "mma.sync.aligned.m16n8k16.row.col.f32.f16.f16.f32 "                  \
        "{%0,%1,%2,%3}, {%4,%5,%6,%7}, {%8,%9}, {%0,%1,%2,%3};"               \
        : "+f"(d0), "+f"(d1), "+f"(d2), "+f"(d3)                              \
        : "r"(a0), "r"(a1), "r"(a2), "r"(a3), "r"(b0), "r"(b1))

#define LDMATRIX_X4(a0, a1, a2, a3, addr)                                     \
    asm volatile(                                                             \
        "ldmatrix.sync.aligned.m8n8.x4.shared.b16 {%0,%1,%2,%3}, [%4];"       \
        : "=r"(a0), "=r"(a1), "=r"(a2), "=r"(a3) : "r"(addr))

// SMEM: 32KB. Phase 1: A tile 64 rows x 256B (XOR-16B swizzle), first 16KB.
// Epilogue: 64 rows x 512B fp32 staging (XOR-32B swizzle), all 32KB.
static constexpr int SMEM_TOTAL = 32768;

// ---------------------------------------------------------------------------
__global__ __launch_bounds__(256, 4) void fused_tanh_gemm_kernel(
    const float* __restrict__ x, const float* __restrict__ tanh_range,
    float* __restrict__ out)
{
    extern __shared__ __align__(16) char smem[];
    uint32_t sbase;
    asm("{ .reg .u64 t; cvta.to.shared.u64 t, %1; cvt.u32.u64 %0, t; }"
        : "=r"(sbase) : "l"(smem));

    const int tid = threadIdx.x;
    const int lane = tid & 31;
    const int wid = tid >> 5;
    const int mgroup = wid >> 2;
    const int ngroup = wid & 3;
    const size_t rowBase = (size_t)blockIdx.x * TILE_M;

    // ---- stage 1: coalesced load + tanh + swizzled STS.64 ----
    // (independent of prep_w output; overlaps with prep_w under PDL)
    {
        const float t = __ldg(tanh_range);
        const float4* x4 = reinterpret_cast<const float4*>(x + rowBase * IDIM);
#pragma unroll
        for (int p = 0; p < 8; p++) {
            int row = wid * 8 + p;
            float4 v = __ldcs(&x4[row * 32 + lane]);
            float t0, t1, t2, t3;
            tanh2(v.x, v.y, t, t0, t1);
            tanh2(v.z, v.w, t, t2, t3);
            uint2 hp;
            hp.x = pack_h2(t0, t1);
            hp.y = pack_h2(t2, t3);
            uint32_t byte = (uint32_t)row * 256 + ((lane * 8) ^ ((row & 7) << 4));
            *reinterpret_cast<uint2*>(smem + byte) = hp;
        }
    }

    // prep_w must be complete before any g_BF read
    cudaGridDependencySynchronize();
    __syncthreads();

    // ---- stage 2: MMA ----
    float acc[2][4][4];
#pragma unroll
    for (int a = 0; a < 2; a++)
#pragma unroll
        for (int b = 0; b < 4; b++)
#pragma unroll
            for (int cc = 0; cc < 4; cc++) acc[a][b][cc] = 0.f;

    const int lrow = ((lane >> 3) & 1) * 8 + (lane & 7);
    const uint32_t chi = (uint32_t)((lane >> 4) << 4);
    const uint32_t sw = (uint32_t)((lane & 7) << 4);
    const uint4* gb = reinterpret_cast<const uint4*>(g_BF);

#pragma unroll
    for (int kt = 0; kt < 8; kt++) {
        uint32_t a0[2], a1[2], a2[2], a3[2];
#pragma unroll
        for (int mt = 0; mt < 2; mt++) {
            int mtg = mgroup * 2 + mt;
            int r = mtg * 16 + lrow;
            uint32_t addr = sbase + (uint32_t)r * 256 + (((uint32_t)kt * 32 + chi) ^ sw);
            LDMATRIX_X4(a0[mt], a1[mt], a2[mt], a3[mt], addr);
        }
#pragma unroll
        for (int j = 0; j < 2; j++) {               // nt pair j -> nt = 2j, 2j+1
            uint4 q = __ldg(&gb[(size_t)((kt * 8 + ngroup * 2 + j) * 32 + lane)]);
#pragma unroll
            for (int mt = 0; mt < 2; mt++) {
                MMA16816(acc[mt][2 * j][0], acc[mt][2 * j][1],
                         acc[mt][2 * j][2], acc[mt][2 * j][3],
                         a0[mt], a1[mt], a2[mt], a3[mt], q.x, q.y);
                MMA16816(acc[mt][2 * j + 1][0], acc[mt][2 * j + 1][1],
                         acc[mt][2 * j + 1][2], acc[mt][2 * j + 1][3],
                         a0[mt], a1[mt], a2[mt], a3[mt], q.z, q.w);
            }
        }
    }

    // ---- epilogue: single restage via 32KB SMEM, coalesced STG ----
    __syncthreads();   // all ldmatrix A-tile reads complete
#pragma unroll
    for (int mt = 0; mt < 2; mt++) {
        int lr = mgroup * 32 + mt * 16 + (lane >> 2);
        int lr2 = lr + 8;
#pragma unroll
        for (int nt = 0; nt < 4; nt++) {
            uint32_t cbyte = (uint32_t)(ngroup * 32 + nt * 8 + ((lane & 3) << 1)) * 4;
            *reinterpret_cast<float2*>(
                smem + lr * 512 + (cbyte ^ ((uint32_t)(lr & 7) << 5)))
                = make_float2(acc[mt][nt][0], acc[mt][nt][1]);
            *reinterpret_cast<float2*>(
                smem + lr2 * 512 + (cbyte ^ ((uint32_t)(lr2 & 7) << 5)))
                = make_float2(acc[mt][nt][2], acc[mt][nt][3]);
        }
    }
    __syncthreads();
    {
        float* obase = out + rowBase * ODIM;
#pragma unroll
        for (int it = 0; it < 8; it++) {
            int idx = tid + it * 256;
            int row = idx >> 5;
            int u = idx & 31;
            uint32_t logical = (uint32_t)u * 16;                       // gmem offset
            uint32_t swz = logical ^ ((uint32_t)(row & 7) << 5);       // smem offset
            uint4 val = *reinterpret_cast<const uint4*>(smem + row * 512 + swz);
            __stcs(reinterpret_cast<uint4*>(
                       reinterpret_cast<char*>(obase + (size_t)row * ODIM) + logical),
                   val);
        }
    }
}

// ---------------------------------------------------------------------------
extern "C" void kernel_launch(void* const* d_in, const int* in_sizes, int n_in,
                              void* d_out, int out_size) {
    const float* x = (const float*)d_in[0];
    const float* coef = (const float*)d_in[1];
    const float* tr = (const float*)d_in[2];
    float* out = (float*)d_out;

    cudaFuncSetAttribute(fused_tanh_gemm_kernel,
                         cudaFuncAttributeMaxDynamicSharedMemorySize, SMEM_TOTAL);

    prep_w_kernel<<<32, 256>>>(coef);

    int rows = in_sizes[0] / IDIM;     // 131072
    int grid = rows / TILE_M;          // 2048

    // PDL: let the GEMM launch/prologue overlap prep_w; device code calls
    // cudaGridDependencySynchronize() before reading g_BF.
    cudaLaunchConfig_t cfg = {};
    cfg.gridDim = dim3((unsigned)grid);
    cfg.blockDim = dim3(256);
    cfg.dynamicSmemBytes = SMEM_TOTAL;
    cfg.stream = 0;
    cudaLaunchAttribute attrs[1];
    attrs[0].id = cudaLaunchAttributeProgrammaticStreamSerialization;
    attrs[0].val.programmaticStreamSerializationAllowed = 1;
    cfg.attrs = attrs;
    cfg.numAttrs = 1;
    cudaLaunchKernelEx(&cfg, fused_tanh_gemm_kernel, x, tr, out);
}